// round 1
// baseline (speedup 1.0000x reference)
#include <cuda_runtime.h>

#define BDIM 1024
#define HDIM 1024
#define DIN  128
#define TLEN 16
#define BH   (BDIM*HDIM)

#define BM 128
#define BN 128
#define BK 16

// ---------------- scratch (device globals; no allocation allowed) ----------------
__device__ float g_ss[BDIM];
__device__ float g_syn[BH];
__device__ float g_ic[BH];
__device__ float g_drive[BH];
__device__ float g_qenh[BH];

// ---------------- f32x2 packed-FMA helpers (Blackwell-only PTX) ----------------
__device__ __forceinline__ unsigned long long pack2(float a) {
    unsigned long long r; unsigned int ai = __float_as_uint(a);
    asm("mov.b64 %0, {%1, %1};" : "=l"(r) : "r"(ai));
    return r;
}
__device__ __forceinline__ void ffma2(unsigned long long& d, unsigned long long a, unsigned long long b) {
    asm("fma.rn.f32x2 %0, %1, %2, %0;" : "+l"(d) : "l"(a), "l"(b));
}
__device__ __forceinline__ float2 unpack2(unsigned long long v) {
    unsigned int lo, hi;
    asm("mov.b64 {%0, %1}, %2;" : "=r"(lo), "=r"(hi) : "l"(v));
    return make_float2(__uint_as_float(lo), __uint_as_float(hi));
}

// ---------------- 1) STDP spike strength: ss[b] = sum_t sh[b,t]*exp(-0.1 t) ----------------
__global__ void ss_kernel(const float* __restrict__ sh) {
    int b = blockIdx.x * blockDim.x + threadIdx.x;
    if (b < BDIM) {
        float acc = 0.0f;
        #pragma unroll
        for (int t = 0; t < TLEN; ++t)
            acc = fmaf(sh[b * TLEN + t], expf(-0.1f * (float)t), acc);
        g_ss[b] = acc;
    }
}

// ---------------- 2) evolved_q = normalize(q*coh + noise*c) -> written straight to d_out slot ----------------
__global__ __launch_bounds__(256) void q_kernel(const float* __restrict__ q,
                                                const float* __restrict__ noise,
                                                float* __restrict__ outq) {
    __shared__ float red[256];
    const int b = blockIdx.x, tid = threadIdx.x;
    const float coh = expf(-0.00066666666666666664f);          // exp(-dt/150)
    const float dec = 0.0015811388300841898f;                  // 0.005*sqrt(0.1)
    float e[4]; float ss = 0.0f;
    #pragma unroll
    for (int it = 0; it < 4; ++it) {
        int idx = b * HDIM + tid + it * 256;
        float v = q[idx] * coh + noise[idx] * dec;
        e[it] = v; ss += v * v;
    }
    red[tid] = ss; __syncthreads();
    for (int s = 128; s > 0; s >>= 1) { if (tid < s) red[tid] += red[tid + s]; __syncthreads(); }
    float denom = sqrtf(red[0]) + 1e-8f;
    #pragma unroll
    for (int it = 0; it < 4; ++it) {
        int idx = b * HDIM + tid + it * 256;
        outq[idx] = e[it] / denom;
    }
}

// ---------------- 3) synaptic einsum with per-b clip: syn = x @ clip(cond + 0.01*ss[b]) ----------------
__global__ __launch_bounds__(256, 2) void syn_kernel(const float* __restrict__ x,
                                                     const float* __restrict__ cond) {
    __shared__ float As[BK][BM];
    __shared__ float Bs[BK][BN];

    const int m0 = blockIdx.y * BM;
    const int n0 = blockIdx.x * BN;
    const int tid = threadIdx.x;
    const int tx = tid & 15, ty = tid >> 4;
    const int arow = tid >> 2, acg = tid & 3;
    const int brow = tid >> 5, bc4 = tid & 31;

    float s[8];
    #pragma unroll
    for (int i = 0; i < 8; ++i) s[i] = g_ss[m0 + ty * 8 + i] * 0.01f;

    float acc[8][8] = {};

    const float* Ab = x + (m0 + arow) * DIN + acg * 4;
    const float* Wb = cond + brow * HDIM + n0 + bc4 * 4;

    float4 ra0 = *(const float4*)(Ab);
    float4 ra1 = *(const float4*)(Ab + 64 * DIN);
    float4 rb0 = *(const float4*)(Wb);
    float4 rb1 = *(const float4*)(Wb + 8 * HDIM);

    const int NT = DIN / BK;  // 8
    for (int kt = 0; kt < NT; ++kt) {
        __syncthreads();
        As[acg * 4 + 0][arow] = ra0.x; As[acg * 4 + 1][arow] = ra0.y;
        As[acg * 4 + 2][arow] = ra0.z; As[acg * 4 + 3][arow] = ra0.w;
        As[acg * 4 + 0][arow + 64] = ra1.x; As[acg * 4 + 1][arow + 64] = ra1.y;
        As[acg * 4 + 2][arow + 64] = ra1.z; As[acg * 4 + 3][arow + 64] = ra1.w;
        *(float4*)&Bs[brow][bc4 * 4]     = rb0;
        *(float4*)&Bs[brow + 8][bc4 * 4] = rb1;
        __syncthreads();
        if (kt + 1 < NT) {
            ra0 = *(const float4*)(Ab + (kt + 1) * BK);
            ra1 = *(const float4*)(Ab + (kt + 1) * BK + 64 * DIN);
            rb0 = *(const float4*)(Wb + (kt + 1) * BK * HDIM);
            rb1 = *(const float4*)(Wb + (kt + 1) * BK * HDIM + 8 * HDIM);
        }
        #pragma unroll
        for (int k = 0; k < BK; ++k) {
            float a[8], b[8];
            *(float4*)&a[0] = *(const float4*)&As[k][ty * 8];
            *(float4*)&a[4] = *(const float4*)&As[k][ty * 8 + 4];
            *(float4*)&b[0] = *(const float4*)&Bs[k][tx * 8];
            *(float4*)&b[4] = *(const float4*)&Bs[k][tx * 8 + 4];
            #pragma unroll
            for (int i = 0; i < 8; ++i) {
                float ai = a[i], si = s[i];
                #pragma unroll
                for (int j = 0; j < 8; ++j) {
                    float cv = fminf(fmaxf(b[j] + si, 0.1f), 3.0f);
                    acc[i][j] = fmaf(ai, cv, acc[i][j]);
                }
            }
        }
    }
    #pragma unroll
    for (int i = 0; i < 8; ++i) {
        float* cp = g_syn + (m0 + ty * 8 + i) * HDIM + n0 + tx * 8;
        *(float4*)cp       = *(float4*)&acc[i][0];
        *(float4*)(cp + 4) = *(float4*)&acc[i][4];
    }
}

// ---------------- 4) the three GEMM products (z selects), f32x2 packed FMA inner loop ----------------
__global__ __launch_bounds__(256, 2) void gemm3_kernel(const float* __restrict__ liquid,
                                                       const float* __restrict__ qn,
                                                       const float* __restrict__ W_l,
                                                       const float* __restrict__ W_r,
                                                       const float* __restrict__ W_s,
                                                       const float* __restrict__ W_ql) {
    __shared__ float As[BK][BM];
    __shared__ float Bs[BK][BN];

    const int z = blockIdx.z;
    const int m0 = blockIdx.y * BM;
    const int n0 = blockIdx.x * BN;
    const int tid = threadIdx.x;
    const int tx = tid & 15, ty = tid >> 4;
    const int arow = tid >> 2, acg = tid & 3;
    const int brow = tid >> 5, bc4 = tid & 31;

    unsigned long long acc[8][4];
    #pragma unroll
    for (int i = 0; i < 8; ++i)
        #pragma unroll
        for (int j = 0; j < 4; ++j) acc[i][j] = 0ULL;

    const float* Alist[2]; const float* Wlist[2]; int npair;
    if (z == 0)      { Alist[0] = g_syn;  Wlist[0] = W_s;  npair = 1; }
    else if (z == 1) { Alist[0] = g_syn;  Wlist[0] = W_l;
                       Alist[1] = liquid; Wlist[1] = W_r;  npair = 2; }
    else             { Alist[0] = qn;     Wlist[0] = W_ql; npair = 1; }

    for (int p = 0; p < npair; ++p) {
        const float* Ab = Alist[p] + (m0 + arow) * HDIM + acg * 4;
        const float* Wb = Wlist[p] + brow * HDIM + n0 + bc4 * 4;

        float4 ra0 = *(const float4*)(Ab);
        float4 ra1 = *(const float4*)(Ab + 64 * HDIM);
        float4 rb0 = *(const float4*)(Wb);
        float4 rb1 = *(const float4*)(Wb + 8 * HDIM);

        const int NT = HDIM / BK;  // 64
        for (int kt = 0; kt < NT; ++kt) {
            __syncthreads();
            As[acg * 4 + 0][arow] = ra0.x; As[acg * 4 + 1][arow] = ra0.y;
            As[acg * 4 + 2][arow] = ra0.z; As[acg * 4 + 3][arow] = ra0.w;
            As[acg * 4 + 0][arow + 64] = ra1.x; As[acg * 4 + 1][arow + 64] = ra1.y;
            As[acg * 4 + 2][arow + 64] = ra1.z; As[acg * 4 + 3][arow + 64] = ra1.w;
            *(float4*)&Bs[brow][bc4 * 4]     = rb0;
            *(float4*)&Bs[brow + 8][bc4 * 4] = rb1;
            __syncthreads();
            if (kt + 1 < NT) {
                ra0 = *(const float4*)(Ab + (kt + 1) * BK);
                ra1 = *(const float4*)(Ab + (kt + 1) * BK + 64 * HDIM);
                rb0 = *(const float4*)(Wb + (kt + 1) * BK * HDIM);
                rb1 = *(const float4*)(Wb + (kt + 1) * BK * HDIM + 8 * HDIM);
            }
            #pragma unroll
            for (int k = 0; k < BK; ++k) {
                const unsigned long long* bp = (const unsigned long long*)&Bs[k][tx * 8];
                unsigned long long b0 = bp[0], b1 = bp[1], b2 = bp[2], b3 = bp[3];
                float a[8];
                *(float4*)&a[0] = *(const float4*)&As[k][ty * 8];
                *(float4*)&a[4] = *(const float4*)&As[k][ty * 8 + 4];
                #pragma unroll
                for (int i = 0; i < 8; ++i) {
                    unsigned long long ap = pack2(a[i]);
                    ffma2(acc[i][0], ap, b0);
                    ffma2(acc[i][1], ap, b1);
                    ffma2(acc[i][2], ap, b2);
                    ffma2(acc[i][3], ap, b3);
                }
            }
        }
    }

    float* C = (z == 0) ? g_ic : (z == 1 ? g_drive : g_qenh);
    #pragma unroll
    for (int i = 0; i < 8; ++i) {
        float2 v0 = unpack2(acc[i][0]);
        float2 v1 = unpack2(acc[i][1]);
        float2 v2 = unpack2(acc[i][2]);
        float2 v3 = unpack2(acc[i][3]);
        float* cp = C + (m0 + ty * 8 + i) * HDIM + n0 + tx * 8;
        *(float4*)cp       = make_float4(v0.x, v0.y, v1.x, v1.y);
        *(float4*)(cp + 4) = make_float4(v2.x, v2.y, v3.x, v3.y);
    }
}

// ---------------- 5) fused elementwise epilogue + spike-mean history ----------------
__global__ __launch_bounds__(256) void final_kernel(const float* __restrict__ mp,
                                                    const float* __restrict__ refr_in,
                                                    const float* __restrict__ liquid,
                                                    const float* __restrict__ taup,
                                                    const float* __restrict__ shist,
                                                    float* __restrict__ out_fused,
                                                    float* __restrict__ out_enh,
                                                    float* __restrict__ out_mem,
                                                    float* __restrict__ out_refr,
                                                    float* __restrict__ out_hist) {
    __shared__ float red[256];
    const int b = blockIdx.x, tid = threadIdx.x;
    const float coh = expf(-0.00066666666666666664f);
    float ssum = 0.0f;
    #pragma unroll
    for (int it = 0; it < 4; ++it) {
        const int h = tid + it * 256;
        const int idx = b * HDIM + h;
        float r = fmaxf(refr_in[idx] - 0.1f, 0.0f);
        bool active = (r == 0.0f);
        float mem = mp[idx] * 0.95f + (active ? g_ic[idx] * 0.1f : 0.0f);
        bool sp = (mem > 0.8f) && active;
        float spike = sp ? 1.0f : 0.0f;
        out_mem[idx]  = sp ? 0.0f : mem;
        out_refr[idx] = sp ? 2.0f : r;
        float sig = 1.0f / (1.0f + expf(-taup[h]));
        float tau = 2.0f + 23.0f * sig;
        float lq = liquid[idx];
        float nl = lq + 0.1f * (tanhf(g_drive[idx]) - lq) / tau;
        float qe = g_qenh[idx] * coh * 0.85f;
        float enh = nl + 0.1f * qe;
        out_enh[idx] = enh;
        out_fused[idx] = spike * (1.0f + 0.1f * tanhf(enh));
        ssum += spike;
    }
    red[tid] = ssum; __syncthreads();
    for (int s = 128; s > 0; s >>= 1) { if (tid < s) red[tid] += red[tid + s]; __syncthreads(); }
    if (tid < TLEN - 1)       out_hist[b * TLEN + tid] = shist[b * TLEN + tid + 1];
    else if (tid == TLEN - 1) out_hist[b * TLEN + TLEN - 1] = red[0] * (1.0f / 1024.0f);
}

// ---------------- launch ----------------
extern "C" void kernel_launch(void* const* d_in, const int* in_sizes, int n_in,
                              void* d_out, int out_size) {
    const float* x      = (const float*)d_in[0];
    const float* liquid = (const float*)d_in[1];
    const float* qstate = (const float*)d_in[2];
    const float* mp     = (const float*)d_in[3];
    const float* refr   = (const float*)d_in[4];
    const float* shist  = (const float*)d_in[5];
    const float* noise  = (const float*)d_in[6];
    const float* cond   = (const float*)d_in[7];
    const float* taup   = (const float*)d_in[8];
    const float* W_l    = (const float*)d_in[9];
    const float* W_r    = (const float*)d_in[10];
    const float* W_s    = (const float*)d_in[11];
    const float* W_ql   = (const float*)d_in[12];

    float* out       = (float*)d_out;
    float* out_fused = out;
    float* out_enh   = out + (size_t)BH;
    float* out_q     = out + (size_t)2 * BH;
    float* out_mem   = out + (size_t)3 * BH;
    float* out_refr  = out + (size_t)4 * BH;
    float* out_hist  = out + (size_t)5 * BH;

    ss_kernel<<<BDIM / 256, 256>>>(shist);
    q_kernel<<<BDIM, 256>>>(qstate, noise, out_q);
    syn_kernel<<<dim3(HDIM / BN, BDIM / BM), 256>>>(x, cond);
    gemm3_kernel<<<dim3(HDIM / BN, BDIM / BM, 3), 256>>>(liquid, out_q, W_l, W_r, W_s, W_ql);
    final_kernel<<<BDIM, 256>>>(mp, refr, liquid, taup, shist,
                                out_fused, out_enh, out_mem, out_refr, out_hist);
}

// round 4
// speedup vs baseline: 2.0257x; 2.0257x over previous
#include <cuda_runtime.h>
#include <cstdint>

#define BDIM 1024
#define HDIM 1024
#define DIN  128
#define TLEN 16
#define BH   (BDIM*HDIM)

// ---------------- device scratch ----------------
__device__ float g_ss[BDIM], g_rs[BDIM];
__device__ float g_x_hi[BDIM*DIN], g_x_lo[BDIM*DIN];
__device__ float g_cT_hi[HDIM*DIN], g_cT_lo[HDIM*DIN];
__device__ float g_WsT_hi[BH], g_WsT_lo[BH], g_WlT[BH], g_WrT[BH], g_WqlT[BH];
__device__ float g_syn_hi[BH], g_syn_lo[BH];
__device__ float g_liqA[BH], g_qA[BH];
__device__ float g_ic[BH], g_drive[BH], g_qenh[BH];
__device__ unsigned g_stats[4];
__device__ int g_noclip;

// ---------------- helpers ----------------
__device__ __forceinline__ float to_tf32(float v) {
    uint32_t u; asm("cvt.rna.tf32.f32 %0, %1;" : "=r"(u) : "f"(v));
    return __uint_as_float(u);
}
__device__ __forceinline__ unsigned fenc(float v) {
    unsigned u = __float_as_uint(v);
    return u ^ (((int)u >> 31) | 0x80000000u);
}
__device__ __forceinline__ float fdec(unsigned k) {
    unsigned u = (k & 0x80000000u) ? (k ^ 0x80000000u) : ~k;
    return __uint_as_float(u);
}
// m16n8k8 tf32 HMMA, fp32 accumulate
__device__ __forceinline__ void mma8(float* d, const uint32_t* a, const uint32_t* b) {
    asm volatile("mma.sync.aligned.m16n8k8.row.col.f32.tf32.tf32.f32 "
                 "{%0,%1,%2,%3}, {%4,%5,%6,%7}, {%8,%9}, {%0,%1,%2,%3};"
                 : "+f"(d[0]), "+f"(d[1]), "+f"(d[2]), "+f"(d[3])
                 : "r"(a[0]), "r"(a[1]), "r"(a[2]), "r"(a[3]), "r"(b[0]), "r"(b[1]));
}

// ---------------- prep kernels ----------------
__global__ void k_init() {
    g_stats[0] = 0xFFFFFFFFu; g_stats[1] = 0u;
    g_stats[2] = 0xFFFFFFFFu; g_stats[3] = 0u;
}

__global__ void k_pre(const float* __restrict__ sh, const float* __restrict__ x) {
    int b = blockIdx.x * 256 + threadIdx.x;
    float ss = 0.f;
    #pragma unroll
    for (int t = 0; t < TLEN; ++t) ss = fmaf(sh[b * TLEN + t], expf(-0.1f * (float)t), ss);
    float rs = 0.f;
    for (int d = 0; d < DIN; ++d) rs += x[b * DIN + d];
    g_ss[b] = ss; g_rs[b] = rs;
    unsigned k = fenc(0.01f * ss), kn = k, kx = k;
    for (int o = 16; o; o >>= 1) {
        kn = min(kn, __shfl_xor_sync(~0u, kn, o));
        kx = max(kx, __shfl_xor_sync(~0u, kx, o));
    }
    if ((threadIdx.x & 31) == 0) { atomicMin(&g_stats[0], kn); atomicMax(&g_stats[1], kx); }
}

__global__ void k_cond(const float* __restrict__ cond) {
    __shared__ float t[32][33];
    int h0 = blockIdx.x * 32, d0 = blockIdx.y * 32;
    int tx = threadIdx.x & 31, ty = threadIdx.x >> 5;
    float ln = 3.4e38f, lx = -3.4e38f;
    #pragma unroll
    for (int r = 0; r < 4; ++r) {
        float v = cond[(d0 + ty + 8 * r) * HDIM + h0 + tx];
        t[ty + 8 * r][tx] = v; ln = fminf(ln, v); lx = fmaxf(lx, v);
    }
    unsigned kn = fenc(ln), kx = fenc(lx);
    for (int o = 16; o; o >>= 1) {
        kn = min(kn, __shfl_xor_sync(~0u, kn, o));
        kx = max(kx, __shfl_xor_sync(~0u, kx, o));
    }
    if ((threadIdx.x & 31) == 0) { atomicMin(&g_stats[2], kn); atomicMax(&g_stats[3], kx); }
    __syncthreads();
    #pragma unroll
    for (int r = 0; r < 4; ++r) {
        float v = t[tx][ty + 8 * r];
        int o = (h0 + ty + 8 * r) * DIN + d0 + tx;
        float hi = to_tf32(v);
        g_cT_hi[o] = hi; g_cT_lo[o] = to_tf32(v - hi);
    }
}

__global__ void k_flag() {
    float smin = fdec(g_stats[0]), smax = fdec(g_stats[1]);
    float cmin = fdec(g_stats[2]), cmax = fdec(g_stats[3]);
    g_noclip = (cmin + smin >= 0.1f && cmax + smax <= 3.0f) ? 1 : 0;
}

__global__ void k_wT(const float* __restrict__ Ws, const float* __restrict__ Wl,
                     const float* __restrict__ Wr, const float* __restrict__ Wql) {
    __shared__ float t[32][33];
    int zz = blockIdx.z;
    const float* W = zz == 0 ? Ws : zz == 1 ? Wl : zz == 2 ? Wr : Wql;
    int n0 = blockIdx.x * 32, k0 = blockIdx.y * 32;
    int tx = threadIdx.x & 31, ty = threadIdx.x >> 5;
    #pragma unroll
    for (int r = 0; r < 4; ++r) t[ty + 8 * r][tx] = W[(k0 + ty + 8 * r) * HDIM + n0 + tx];
    __syncthreads();
    #pragma unroll
    for (int r = 0; r < 4; ++r) {
        float v = t[tx][ty + 8 * r];
        int o = (n0 + ty + 8 * r) * HDIM + k0 + tx;
        float hi = to_tf32(v);
        if (zz == 0) { g_WsT_hi[o] = hi; g_WsT_lo[o] = to_tf32(v - hi); }
        else if (zz == 1) g_WlT[o] = hi;
        else if (zz == 2) g_WrT[o] = hi;
        else g_WqlT[o] = hi;
    }
}

__global__ void k_misc(const float* __restrict__ x, const float* __restrict__ liq) {
    int i = blockIdx.x * 256 + threadIdx.x;
    g_liqA[i] = to_tf32(liq[i]);
    if (i < BDIM * DIN) {
        float v = x[i], hi = to_tf32(v);
        g_x_hi[i] = hi; g_x_lo[i] = to_tf32(v - hi);
    }
}

__global__ __launch_bounds__(256) void k_qnorm(const float* __restrict__ q,
                                               const float* __restrict__ noise,
                                               float* __restrict__ outq) {
    __shared__ float red[256];
    const int b = blockIdx.x, tid = threadIdx.x;
    const float coh = expf(-0.00066666666666666664f);
    const float dec = 0.0015811388300841898f;
    float e[4]; float ss = 0.f;
    #pragma unroll
    for (int it = 0; it < 4; ++it) {
        int idx = b * HDIM + tid + it * 256;
        float v = q[idx] * coh + noise[idx] * dec;
        e[it] = v; ss += v * v;
    }
    red[tid] = ss; __syncthreads();
    for (int s = 128; s > 0; s >>= 1) { if (tid < s) red[tid] += red[tid + s]; __syncthreads(); }
    float den = sqrtf(red[0]) + 1e-8f;
    #pragma unroll
    for (int it = 0; it < 4; ++it) {
        int idx = b * HDIM + tid + it * 256;
        float v = e[it] / den;
        outq[idx] = v;
        g_qA[idx] = to_tf32(v);
    }
}

// exact SIMT fallback if clipping is actually possible (skipped when g_noclip)
__global__ __launch_bounds__(256) void k_syn_fb(const float* __restrict__ x,
                                                const float* __restrict__ cond) {
    if (g_noclip) return;
    __shared__ float xs[DIN];
    int b = blockIdx.x;
    if (threadIdx.x < DIN) xs[threadIdx.x] = x[b * DIN + threadIdx.x];
    __syncthreads();
    float s = 0.01f * g_ss[b];
    for (int h = threadIdx.x; h < HDIM; h += 256) {
        float acc = 0.f;
        for (int d = 0; d < DIN; ++d)
            acc = fmaf(xs[d], fminf(fmaxf(cond[d * HDIM + h] + s, 0.1f), 3.0f), acc);
        float hi = to_tf32(acc);
        g_syn_hi[b * HDIM + h] = hi;
        g_syn_lo[b * HDIM + h] = to_tf32(acc - hi);
    }
}

// ---------------- mma.sync tf32 GEMM ----------------
// mode 0: z=0 ic (3 segs K=1024), z=1 drive (2 segs), z=2 qenh (1 seg)
// mode 1: syn = 3-term x@condT (3 segs K=128), + rank-1 corr, split-write
__global__ __launch_bounds__(256, 1) void k_mma(int mode) {
    if (mode == 1 && !g_noclip) return;
    __shared__ float As[128][36];
    __shared__ float Bs[128][36];

    const int tid = threadIdx.x, wid = tid >> 5, lane = tid & 31;
    const int m0 = blockIdx.y * 128, n0 = blockIdx.x * 128;
    const int wm0 = (wid & 1) * 64, wn0 = (wid >> 1) * 32;
    const int row = lane >> 2, t4 = lane & 3;
    const int z = blockIdx.z;

    const float *Aseg[3], *Bseg[3];
    int nseg, ldA, ipern;
    if (mode == 0) {
        ldA = HDIM; ipern = 32;
        if (z == 0) {
            Aseg[0] = g_syn_hi; Bseg[0] = g_WsT_hi;
            Aseg[1] = g_syn_lo; Bseg[1] = g_WsT_hi;
            Aseg[2] = g_syn_hi; Bseg[2] = g_WsT_lo;
            nseg = 3;
        } else if (z == 1) {
            Aseg[0] = g_syn_hi; Bseg[0] = g_WlT;
            Aseg[1] = g_liqA;   Bseg[1] = g_WrT;
            nseg = 2;
        } else {
            Aseg[0] = g_qA; Bseg[0] = g_WqlT;
            nseg = 1;
        }
    } else {
        ldA = DIN; ipern = 4;
        Aseg[0] = g_x_hi; Bseg[0] = g_cT_hi;
        Aseg[1] = g_x_lo; Bseg[1] = g_cT_hi;
        Aseg[2] = g_x_hi; Bseg[2] = g_cT_lo;
        nseg = 3;
    }
    const int NT = nseg * ipern;

    float acc[4][4][4];
    #pragma unroll
    for (int a = 0; a < 4; ++a)
        #pragma unroll
        for (int b = 0; b < 4; ++b)
            #pragma unroll
            for (int c = 0; c < 4; ++c) acc[a][b][c] = 0.f;

    float4 ra[4], rb[4];
    {   // prefetch iter 0
        const float* Ap = Aseg[0]; const float* Bp = Bseg[0];
        #pragma unroll
        for (int i = 0; i < 4; ++i) {
            int idx = tid + (i << 8), r = idx >> 3, c = idx & 7;
            ra[i] = *(const float4*)(Ap + (m0 + r) * ldA + c * 4);
            rb[i] = *(const float4*)(Bp + (n0 + r) * ldA + c * 4);
        }
    }

    #pragma unroll 1
    for (int it = 0; it < NT; ++it) {
        #pragma unroll
        for (int i = 0; i < 4; ++i) {
            int idx = tid + (i << 8), r = idx >> 3, c = idx & 7;
            *(float4*)&As[r][c * 4] = ra[i];
            *(float4*)&Bs[r][c * 4] = rb[i];
        }
        __syncthreads();
        if (it + 1 < NT) {
            int seg = (it + 1) / ipern, kk = ((it + 1) % ipern) * 32;
            const float* Ap = Aseg[seg]; const float* Bp = Bseg[seg];
            #pragma unroll
            for (int i = 0; i < 4; ++i) {
                int idx = tid + (i << 8), r = idx >> 3, c = idx & 7;
                ra[i] = *(const float4*)(Ap + (m0 + r) * ldA + kk + c * 4);
                rb[i] = *(const float4*)(Bp + (n0 + r) * ldA + kk + c * 4);
            }
        }
        #pragma unroll
        for (int kc = 0; kc < 4; ++kc) {
            const int kb = kc * 8;
            uint32_t af[4][4], bf[4][2];
            #pragma unroll
            for (int mt = 0; mt < 4; ++mt) {
                int m = wm0 + mt * 16 + row;
                af[mt][0] = __float_as_uint(As[m][kb + t4]);
                af[mt][1] = __float_as_uint(As[m + 8][kb + t4]);
                af[mt][2] = __float_as_uint(As[m][kb + t4 + 4]);
                af[mt][3] = __float_as_uint(As[m + 8][kb + t4 + 4]);
            }
            #pragma unroll
            for (int nt = 0; nt < 4; ++nt) {
                int n = wn0 + nt * 8 + row;
                bf[nt][0] = __float_as_uint(Bs[n][kb + t4]);
                bf[nt][1] = __float_as_uint(Bs[n][kb + t4 + 4]);
            }
            #pragma unroll
            for (int mt = 0; mt < 4; ++mt)
                #pragma unroll
                for (int nt = 0; nt < 4; ++nt)
                    mma8(acc[mt][nt], af[mt], bf[nt]);
        }
        __syncthreads();
    }

    if (mode == 0) {
        float* C = z == 0 ? g_ic : (z == 1 ? g_drive : g_qenh);
        #pragma unroll
        for (int mt = 0; mt < 4; ++mt) {
            int m = m0 + wm0 + mt * 16 + row;
            #pragma unroll
            for (int nt = 0; nt < 4; ++nt) {
                int n = n0 + wn0 + nt * 8 + t4 * 2;
                *(float2*)(C + (size_t)m * HDIM + n) =
                    make_float2(acc[mt][nt][0], acc[mt][nt][1]);
                *(float2*)(C + (size_t)(m + 8) * HDIM + n) =
                    make_float2(acc[mt][nt][2], acc[mt][nt][3]);
            }
        }
    } else {
        #pragma unroll
        for (int mt = 0; mt < 4; ++mt) {
            int m = m0 + wm0 + mt * 16 + row;
            float c0 = 0.01f * g_ss[m] * g_rs[m];
            float c1 = 0.01f * g_ss[m + 8] * g_rs[m + 8];
            #pragma unroll
            for (int nt = 0; nt < 4; ++nt) {
                int n = n0 + wn0 + nt * 8 + t4 * 2;
                #pragma unroll
                for (int e = 0; e < 4; ++e) {
                    int mm = (e < 2) ? m : m + 8;
                    float corr = (e < 2) ? c0 : c1;
                    float v = acc[mt][nt][e] + corr;
                    float hi = to_tf32(v);
                    size_t o = (size_t)mm * HDIM + n + (e & 1);
                    g_syn_hi[o] = hi;
                    g_syn_lo[o] = to_tf32(v - hi);
                }
            }
        }
    }
}

// ---------------- final fused epilogue ----------------
__global__ __launch_bounds__(256) void k_final(const float* __restrict__ mp,
                                               const float* __restrict__ refr_in,
                                               const float* __restrict__ liquid,
                                               const float* __restrict__ taup,
                                               const float* __restrict__ shist,
                                               float* __restrict__ out_fused,
                                               float* __restrict__ out_enh,
                                               float* __restrict__ out_mem,
                                               float* __restrict__ out_refr,
                                               float* __restrict__ out_hist) {
    __shared__ float red[256];
    const int b = blockIdx.x, tid = threadIdx.x;
    const float coh = expf(-0.00066666666666666664f);
    float ssum = 0.f;
    #pragma unroll
    for (int it = 0; it < 4; ++it) {
        const int h = tid + it * 256, idx = b * HDIM + h;
        float ic = g_ic[idx];
        float drive = g_drive[idx];
        float r = fmaxf(refr_in[idx] - 0.1f, 0.f);
        bool act = (r == 0.f);
        float mem = mp[idx] * 0.95f + (act ? ic * 0.1f : 0.f);
        bool sp = (mem > 0.8f) && act;
        float spike = sp ? 1.f : 0.f;
        out_mem[idx] = sp ? 0.f : mem;
        out_refr[idx] = sp ? 2.f : r;
        float sig = 1.f / (1.f + expf(-taup[h]));
        float tau = 2.f + 23.f * sig;
        float lq = liquid[idx];
        float nl = lq + 0.1f * (tanhf(drive) - lq) / tau;
        float enh = nl + 0.1f * (g_qenh[idx] * coh * 0.85f);
        out_enh[idx] = enh;
        out_fused[idx] = spike * (1.f + 0.1f * tanhf(enh));
        ssum += spike;
    }
    red[tid] = ssum; __syncthreads();
    for (int s = 128; s > 0; s >>= 1) { if (tid < s) red[tid] += red[tid + s]; __syncthreads(); }
    if (tid < TLEN - 1)       out_hist[b * TLEN + tid] = shist[b * TLEN + tid + 1];
    else if (tid == TLEN - 1) out_hist[b * TLEN + TLEN - 1] = red[0] * (1.0f / 1024.0f);
}

// ---------------- launch ----------------
extern "C" void kernel_launch(void* const* d_in, const int* in_sizes, int n_in,
                              void* d_out, int out_size) {
    const float* x      = (const float*)d_in[0];
    const float* liquid = (const float*)d_in[1];
    const float* qstate = (const float*)d_in[2];
    const float* mp     = (const float*)d_in[3];
    const float* refr   = (const float*)d_in[4];
    const float* shist  = (const float*)d_in[5];
    const float* noise  = (const float*)d_in[6];
    const float* cond   = (const float*)d_in[7];
    const float* taup   = (const float*)d_in[8];
    const float* W_l    = (const float*)d_in[9];
    const float* W_r    = (const float*)d_in[10];
    const float* W_s    = (const float*)d_in[11];
    const float* W_ql   = (const float*)d_in[12];

    float* out       = (float*)d_out;
    float* out_fused = out;
    float* out_enh   = out + (size_t)BH;
    float* out_q     = out + (size_t)2 * BH;
    float* out_mem   = out + (size_t)3 * BH;
    float* out_refr  = out + (size_t)4 * BH;
    float* out_hist  = out + (size_t)5 * BH;

    k_init<<<1, 1>>>();
    k_pre<<<BDIM / 256, 256>>>(shist, x);
    k_cond<<<dim3(32, 4), 256>>>(cond);
    k_flag<<<1, 1>>>();
    k_wT<<<dim3(32, 32, 4), 256>>>(W_s, W_l, W_r, W_ql);
    k_misc<<<BH / 256, 256>>>(x, liquid);
    k_qnorm<<<BDIM, 256>>>(qstate, noise, out_q);
    k_mma<<<dim3(8, 8), 256>>>(1);
    k_syn_fb<<<BDIM, 256>>>(x, cond);
    k_mma<<<dim3(8, 8, 3), 256>>>(0);
    k_final<<<BDIM, 256>>>(mp, refr, liquid, taup, shist,
                           out_fused, out_enh, out_mem, out_refr, out_hist);
}

// round 5
// speedup vs baseline: 2.3661x; 1.1681x over previous
#include <cuda_runtime.h>
#include <cstdint>

#define BDIM 1024
#define HDIM 1024
#define DIN  128
#define TLEN 16
#define BH   (BDIM*HDIM)

// ---------------- device scratch ----------------
__device__ float g_ss[BDIM], g_rs[BDIM];
__device__ float g_x_hi[BDIM*DIN], g_x_lo[BDIM*DIN];
__device__ float g_cT_hi[HDIM*DIN], g_cT_lo[HDIM*DIN];
__device__ float g_WsT_hi[BH], g_WsT_lo[BH], g_WlT[BH], g_WrT[BH], g_WqlT[BH];
__device__ float g_syn_hi[BH], g_syn_lo[BH];
__device__ float g_liqA[BH], g_qA[BH];
__device__ float g_ic[BH], g_drive[BH], g_qenh[BH];
__device__ unsigned g_sp_min[4], g_sp_max[4];       // spike-shift partial stats (4 blocks)
__device__ unsigned g_cp_min[128], g_cp_max[128];   // cond partial stats (128 blocks)

// ---------------- helpers ----------------
__device__ __forceinline__ float to_tf32(float v) {
    uint32_t u; asm("cvt.rna.tf32.f32 %0, %1;" : "=r"(u) : "f"(v));
    return __uint_as_float(u);
}
__device__ __forceinline__ unsigned fenc(float v) {
    unsigned u = __float_as_uint(v);
    return u ^ (((int)u >> 31) | 0x80000000u);
}
__device__ __forceinline__ float fdec(unsigned k) {
    unsigned u = (k & 0x80000000u) ? (k ^ 0x80000000u) : ~k;
    return __uint_as_float(u);
}
__device__ __forceinline__ void mma8(float* d, const uint32_t* a, const uint32_t* b) {
    asm volatile("mma.sync.aligned.m16n8k8.row.col.f32.tf32.tf32.f32 "
                 "{%0,%1,%2,%3}, {%4,%5,%6,%7}, {%8,%9}, {%0,%1,%2,%3};"
                 : "+f"(d[0]), "+f"(d[1]), "+f"(d[2]), "+f"(d[3])
                 : "r"(a[0]), "r"(a[1]), "r"(a[2]), "r"(a[3]), "r"(b[0]), "r"(b[1]));
}
__device__ __forceinline__ int compute_noclip() {
    unsigned sn = 0xFFFFFFFFu, sx = 0u, cn = 0xFFFFFFFFu, cx = 0u;
    #pragma unroll
    for (int i = 0; i < 4; ++i) { sn = min(sn, g_sp_min[i]); sx = max(sx, g_sp_max[i]); }
    for (int i = 0; i < 128; ++i) { cn = min(cn, g_cp_min[i]); cx = max(cx, g_cp_max[i]); }
    float smin = fdec(sn), smax = fdec(sx), cmin = fdec(cn), cmax = fdec(cx);
    return (cmin + smin >= 0.1f && cmax + smax <= 3.0f) ? 1 : 0;
}

// ======================================================================
// k_prep: all independent prep work in ONE launch, role by blockIdx.x
//   [0,4)        : ss/rs + spike-shift stats
//   [4,132)      : cond transpose+split + cond stats
//   [132,4228)   : weight transpose (+split for Ws)
//   [4228,8324)  : liq tf32 round + x split
//   [8324,9348)  : quantum normalize (writes out_q directly) + tf32 round
// ======================================================================
#define PREP_BLOCKS 9348
__global__ __launch_bounds__(256) void k_prep(const float* __restrict__ x,
                                              const float* __restrict__ liq,
                                              const float* __restrict__ q,
                                              const float* __restrict__ noise,
                                              const float* __restrict__ sh,
                                              const float* __restrict__ cond,
                                              const float* __restrict__ Ws,
                                              const float* __restrict__ Wl,
                                              const float* __restrict__ Wr,
                                              const float* __restrict__ Wql,
                                              float* __restrict__ outq) {
    __shared__ float t[32][33];
    __shared__ unsigned redn[256], redx[256];
    const int bid = blockIdx.x, tid = threadIdx.x;

    if (bid < 4) {                                  // ---- role: ss/rs + stats
        int b = bid * 256 + tid;
        float ss = 0.f;
        #pragma unroll
        for (int tt = 0; tt < TLEN; ++tt)
            ss = fmaf(sh[b * TLEN + tt], expf(-0.1f * (float)tt), ss);
        float rs = 0.f;
        for (int d = 0; d < DIN; ++d) rs += x[b * DIN + d];
        g_ss[b] = ss; g_rs[b] = rs;
        unsigned k = fenc(0.01f * ss);
        redn[tid] = k; redx[tid] = k; __syncthreads();
        for (int s = 128; s > 0; s >>= 1) {
            if (tid < s) { redn[tid] = min(redn[tid], redn[tid + s]); redx[tid] = max(redx[tid], redx[tid + s]); }
            __syncthreads();
        }
        if (tid == 0) { g_sp_min[bid] = redn[0]; g_sp_max[bid] = redx[0]; }
    } else if (bid < 132) {                         // ---- role: cond T+split + stats
        int i = bid - 4;
        int h0 = (i & 31) * 32, d0 = (i >> 5) * 32;
        int tx = tid & 31, ty = tid >> 5;
        float ln = 3.4e38f, lx = -3.4e38f;
        #pragma unroll
        for (int r = 0; r < 4; ++r) {
            float v = cond[(d0 + ty + 8 * r) * HDIM + h0 + tx];
            t[ty + 8 * r][tx] = v; ln = fminf(ln, v); lx = fmaxf(lx, v);
        }
        redn[tid] = fenc(ln); redx[tid] = fenc(lx); __syncthreads();
        for (int s = 128; s > 0; s >>= 1) {
            if (tid < s) { redn[tid] = min(redn[tid], redn[tid + s]); redx[tid] = max(redx[tid], redx[tid + s]); }
            __syncthreads();
        }
        if (tid == 0) { g_cp_min[i] = redn[0]; g_cp_max[i] = redx[0]; }
        #pragma unroll
        for (int r = 0; r < 4; ++r) {
            float v = t[tx][ty + 8 * r];
            int o = (h0 + ty + 8 * r) * DIN + d0 + tx;
            float hi = to_tf32(v);
            g_cT_hi[o] = hi; g_cT_lo[o] = to_tf32(v - hi);
        }
    } else if (bid < 4228) {                        // ---- role: weight transpose
        int i = bid - 132;
        int zz = i >> 10, rem = i & 1023;
        const float* W = zz == 0 ? Ws : zz == 1 ? Wl : zz == 2 ? Wr : Wql;
        int n0 = (rem & 31) * 32, k0 = (rem >> 5) * 32;
        int tx = tid & 31, ty = tid >> 5;
        #pragma unroll
        for (int r = 0; r < 4; ++r) t[ty + 8 * r][tx] = W[(k0 + ty + 8 * r) * HDIM + n0 + tx];
        __syncthreads();
        #pragma unroll
        for (int r = 0; r < 4; ++r) {
            float v = t[tx][ty + 8 * r];
            int o = (n0 + ty + 8 * r) * HDIM + k0 + tx;
            float hi = to_tf32(v);
            if (zz == 0) { g_WsT_hi[o] = hi; g_WsT_lo[o] = to_tf32(v - hi); }
            else if (zz == 1) g_WlT[o] = hi;
            else if (zz == 2) g_WrT[o] = hi;
            else g_WqlT[o] = hi;
        }
    } else if (bid < 8324) {                        // ---- role: liq round + x split
        int i = (bid - 4228) * 256 + tid;
        g_liqA[i] = to_tf32(liq[i]);
        if (i < BDIM * DIN) {
            float v = x[i], hi = to_tf32(v);
            g_x_hi[i] = hi; g_x_lo[i] = to_tf32(v - hi);
        }
    } else {                                        // ---- role: qnorm
        __shared__ float red[256];
        int b = bid - 8324;
        const float coh = expf(-0.00066666666666666664f);
        const float dec = 0.0015811388300841898f;
        float e[4]; float ss = 0.f;
        #pragma unroll
        for (int it = 0; it < 4; ++it) {
            int idx = b * HDIM + tid + it * 256;
            float v = q[idx] * coh + noise[idx] * dec;
            e[it] = v; ss += v * v;
        }
        red[tid] = ss; __syncthreads();
        for (int s = 128; s > 0; s >>= 1) { if (tid < s) red[tid] += red[tid + s]; __syncthreads(); }
        float den = sqrtf(red[0]) + 1e-8f;
        #pragma unroll
        for (int it = 0; it < 4; ++it) {
            int idx = b * HDIM + tid + it * 256;
            float v = e[it] / den;
            outq[idx] = v;
            g_qA[idx] = to_tf32(v);
        }
    }
}

// ======================================================================
// k_mma: double-buffered tf32 mma.sync GEMM
//   mode 0: z=0 ic (3 segs);  z=1 drive (2 segs, flush) + qenh (1 seg, flush)
//   mode 1: syn 3-term x@cT (K=128 segs) + rank-1 corr, split write
//           (contains exact SIMT fallback if clipping possible)
// ======================================================================
#define SMS 36                       // smem row stride (floats)
#define ABUF 4608                    // 128*36
#define BUFSZ 9216                   // A + B
#define GSMEM (2 * BUFSZ * 4)        // 73728 bytes

__global__ __launch_bounds__(256, 1) void k_mma(int mode, const float* __restrict__ x,
                                                const float* __restrict__ cond) {
    extern __shared__ float sm[];
    __shared__ int s_noclip;
    const int tid = threadIdx.x, wid = tid >> 5, lane = tid & 31;
    const int m0 = blockIdx.y * 128, n0 = blockIdx.x * 128;
    const int wm0 = (wid & 1) * 64, wn0 = (wid >> 1) * 32;
    const int row = lane >> 2, t4 = lane & 3;
    const int z = blockIdx.z;

    if (mode == 1) {
        if (tid == 0) s_noclip = compute_noclip();
        __syncthreads();
        if (!s_noclip) {
            // exact SIMT fallback (clip can bind): correctness path only
            int m = m0 + (tid & 127), nh = tid >> 7;
            float s = 0.01f * g_ss[m];
            for (int n = n0 + nh * 64; n < n0 + nh * 64 + 64; ++n) {
                float acc = 0.f;
                for (int d = 0; d < DIN; ++d)
                    acc = fmaf(x[m * DIN + d], fminf(fmaxf(cond[d * HDIM + n] + s, 0.1f), 3.0f), acc);
                float hi = to_tf32(acc);
                g_syn_hi[(size_t)m * HDIM + n] = hi;
                g_syn_lo[(size_t)m * HDIM + n] = to_tf32(acc - hi);
            }
            return;
        }
    }

    const float *Aseg[3], *Bseg[3];
    float* Cf[3] = {nullptr, nullptr, nullptr};
    int nseg, ldA, ipern;
    if (mode == 0) {
        ldA = HDIM; ipern = 32;
        if (z == 0) {
            Aseg[0] = g_syn_hi; Bseg[0] = g_WsT_hi;
            Aseg[1] = g_syn_lo; Bseg[1] = g_WsT_hi;
            Aseg[2] = g_syn_hi; Bseg[2] = g_WsT_lo;
            Cf[2] = g_ic; nseg = 3;
        } else {
            Aseg[0] = g_syn_hi; Bseg[0] = g_WlT;
            Aseg[1] = g_liqA;   Bseg[1] = g_WrT;
            Aseg[2] = g_qA;     Bseg[2] = g_WqlT;
            Cf[1] = g_drive; Cf[2] = g_qenh; nseg = 3;
        }
    } else {
        ldA = DIN; ipern = 4;
        Aseg[0] = g_x_hi; Bseg[0] = g_cT_hi;
        Aseg[1] = g_x_lo; Bseg[1] = g_cT_hi;
        Aseg[2] = g_x_hi; Bseg[2] = g_cT_lo;
        nseg = 3;
    }
    const int NT = nseg * ipern;

    float acc[4][4][4];
    #pragma unroll
    for (int a = 0; a < 4; ++a)
        #pragma unroll
        for (int b = 0; b < 4; ++b)
            #pragma unroll
            for (int c = 0; c < 4; ++c) acc[a][b][c] = 0.f;

    const int lr = tid >> 3, lc = tid & 7;   // load coords: 32 rows per pass, 8 float4 cols
    float4 ra[4], rb[4];
    {   // iter 0 -> buffer 0
        const float* Ap = Aseg[0]; const float* Bp = Bseg[0];
        #pragma unroll
        for (int i = 0; i < 4; ++i) {
            int r = lr + i * 32;
            ra[i] = *(const float4*)(Ap + (size_t)(m0 + r) * ldA + lc * 4);
            rb[i] = *(const float4*)(Bp + (size_t)(n0 + r) * ldA + lc * 4);
        }
        #pragma unroll
        for (int i = 0; i < 4; ++i) {
            int r = lr + i * 32;
            *(float4*)&sm[r * SMS + lc * 4] = ra[i];
            *(float4*)&sm[ABUF + r * SMS + lc * 4] = rb[i];
        }
    }
    __syncthreads();

    #pragma unroll 1
    for (int it = 0; it < NT; ++it) {
        const int cur = it & 1;
        float* As = sm + cur * BUFSZ;
        float* Bs = sm + cur * BUFSZ + ABUF;
        if (it + 1 < NT) {
            int seg = (it + 1) / ipern, kk = ((it + 1) % ipern) * 32;
            const float* Ap = Aseg[seg]; const float* Bp = Bseg[seg];
            #pragma unroll
            for (int i = 0; i < 4; ++i) {
                int r = lr + i * 32;
                ra[i] = *(const float4*)(Ap + (size_t)(m0 + r) * ldA + kk + lc * 4);
                rb[i] = *(const float4*)(Bp + (size_t)(n0 + r) * ldA + kk + lc * 4);
            }
        }
        #pragma unroll
        for (int kc = 0; kc < 4; ++kc) {
            const int kb = kc * 8;
            uint32_t af[4][4], bf[4][2];
            #pragma unroll
            for (int mt = 0; mt < 4; ++mt) {
                int m = wm0 + mt * 16 + row;
                af[mt][0] = __float_as_uint(As[m * SMS + kb + t4]);
                af[mt][1] = __float_as_uint(As[(m + 8) * SMS + kb + t4]);
                af[mt][2] = __float_as_uint(As[m * SMS + kb + t4 + 4]);
                af[mt][3] = __float_as_uint(As[(m + 8) * SMS + kb + t4 + 4]);
            }
            #pragma unroll
            for (int nt = 0; nt < 4; ++nt) {
                int n = wn0 + nt * 8 + row;
                bf[nt][0] = __float_as_uint(Bs[n * SMS + kb + t4]);
                bf[nt][1] = __float_as_uint(Bs[n * SMS + kb + t4 + 4]);
            }
            #pragma unroll
            for (int mt = 0; mt < 4; ++mt)
                #pragma unroll
                for (int nt = 0; nt < 4; ++nt)
                    mma8(acc[mt][nt], af[mt], bf[nt]);
        }
        // segment flush (mode 0)
        if (mode == 0 && ((it + 1) % ipern == 0)) {
            float* C = Cf[it / ipern];
            if (C) {
                #pragma unroll
                for (int mt = 0; mt < 4; ++mt) {
                    int m = m0 + wm0 + mt * 16 + row;
                    #pragma unroll
                    for (int nt = 0; nt < 4; ++nt) {
                        int n = n0 + wn0 + nt * 8 + t4 * 2;
                        *(float2*)(C + (size_t)m * HDIM + n) = make_float2(acc[mt][nt][0], acc[mt][nt][1]);
                        *(float2*)(C + (size_t)(m + 8) * HDIM + n) = make_float2(acc[mt][nt][2], acc[mt][nt][3]);
                    }
                }
                #pragma unroll
                for (int a = 0; a < 4; ++a)
                    #pragma unroll
                    for (int b = 0; b < 4; ++b)
                        #pragma unroll
                        for (int c = 0; c < 4; ++c) acc[a][b][c] = 0.f;
            }
        }
        if (it + 1 < NT) {
            float* An = sm + (cur ^ 1) * BUFSZ;
            float* Bn = sm + (cur ^ 1) * BUFSZ + ABUF;
            #pragma unroll
            for (int i = 0; i < 4; ++i) {
                int r = lr + i * 32;
                *(float4*)&An[r * SMS + lc * 4] = ra[i];
                *(float4*)&Bn[r * SMS + lc * 4] = rb[i];
            }
        }
        __syncthreads();
    }

    if (mode == 1) {   // syn epilogue: rank-1 correction + tf32 split write
        #pragma unroll
        for (int mt = 0; mt < 4; ++mt) {
            int m = m0 + wm0 + mt * 16 + row;
            float c0 = 0.01f * g_ss[m] * g_rs[m];
            float c1 = 0.01f * g_ss[m + 8] * g_rs[m + 8];
            #pragma unroll
            for (int nt = 0; nt < 4; ++nt) {
                int n = n0 + wn0 + nt * 8 + t4 * 2;
                #pragma unroll
                for (int e = 0; e < 4; ++e) {
                    int mm = (e < 2) ? m : m + 8;
                    float v = acc[mt][nt][e] + ((e < 2) ? c0 : c1);
                    float hi = to_tf32(v);
                    size_t o = (size_t)mm * HDIM + n + (e & 1);
                    g_syn_hi[o] = hi;
                    g_syn_lo[o] = to_tf32(v - hi);
                }
            }
        }
    }
}

// ---------------- final fused epilogue ----------------
__global__ __launch_bounds__(256) void k_final(const float* __restrict__ mp,
                                               const float* __restrict__ refr_in,
                                               const float* __restrict__ liquid,
                                               const float* __restrict__ taup,
                                               const float* __restrict__ shist,
                                               float* __restrict__ out_fused,
                                               float* __restrict__ out_enh,
                                               float* __restrict__ out_mem,
                                               float* __restrict__ out_refr,
                                               float* __restrict__ out_hist) {
    __shared__ float red[256];
    const int b = blockIdx.x, tid = threadIdx.x;
    const float coh = expf(-0.00066666666666666664f);
    float ssum = 0.f;
    #pragma unroll
    for (int it = 0; it < 4; ++it) {
        const int h = tid + it * 256, idx = b * HDIM + h;
        float ic = g_ic[idx];
        float drive = g_drive[idx];
        float r = fmaxf(refr_in[idx] - 0.1f, 0.f);
        bool act = (r == 0.f);
        float mem = mp[idx] * 0.95f + (act ? ic * 0.1f : 0.f);
        bool sp = (mem > 0.8f) && act;
        float spike = sp ? 1.f : 0.f;
        out_mem[idx] = sp ? 0.f : mem;
        out_refr[idx] = sp ? 2.f : r;
        float sig = 1.f / (1.f + expf(-taup[h]));
        float tau = 2.f + 23.f * sig;
        float lq = liquid[idx];
        float nl = lq + 0.1f * (tanhf(drive) - lq) / tau;
        float enh = nl + 0.1f * (g_qenh[idx] * coh * 0.85f);
        out_enh[idx] = enh;
        out_fused[idx] = spike * (1.f + 0.1f * tanhf(enh));
        ssum += spike;
    }
    red[tid] = ssum; __syncthreads();
    for (int s = 128; s > 0; s >>= 1) { if (tid < s) red[tid] += red[tid + s]; __syncthreads(); }
    if (tid < TLEN - 1)       out_hist[b * TLEN + tid] = shist[b * TLEN + tid + 1];
    else if (tid == TLEN - 1) out_hist[b * TLEN + TLEN - 1] = red[0] * (1.0f / 1024.0f);
}

// ---------------- launch ----------------
extern "C" void kernel_launch(void* const* d_in, const int* in_sizes, int n_in,
                              void* d_out, int out_size) {
    const float* x      = (const float*)d_in[0];
    const float* liquid = (const float*)d_in[1];
    const float* qstate = (const float*)d_in[2];
    const float* mp     = (const float*)d_in[3];
    const float* refr   = (const float*)d_in[4];
    const float* shist  = (const float*)d_in[5];
    const float* noise  = (const float*)d_in[6];
    const float* cond   = (const float*)d_in[7];
    const float* taup   = (const float*)d_in[8];
    const float* W_l    = (const float*)d_in[9];
    const float* W_r    = (const float*)d_in[10];
    const float* W_s    = (const float*)d_in[11];
    const float* W_ql   = (const float*)d_in[12];

    float* out       = (float*)d_out;
    float* out_fused = out;
    float* out_enh   = out + (size_t)BH;
    float* out_q     = out + (size_t)2 * BH;
    float* out_mem   = out + (size_t)3 * BH;
    float* out_refr  = out + (size_t)4 * BH;
    float* out_hist  = out + (size_t)5 * BH;

    static int smem_set = 0;
    if (!smem_set) {
        cudaFuncSetAttribute(k_mma, cudaFuncAttributeMaxDynamicSharedMemorySize, GSMEM);
        smem_set = 1;
    }

    k_prep<<<PREP_BLOCKS, 256>>>(x, liquid, qstate, noise, shist, cond,
                                 W_s, W_l, W_r, W_ql, out_q);
    k_mma<<<dim3(8, 8), 256, GSMEM>>>(1, x, cond);
    k_mma<<<dim3(8, 8, 2), 256, GSMEM>>>(0, x, cond);
    k_final<<<BDIM, 256>>>(mp, refr, liquid, taup, shist,
                           out_fused, out_enh, out_mem, out_refr, out_hist);
}

// round 6
// speedup vs baseline: 2.8337x; 1.1976x over previous
#include <cuda_runtime.h>
#include <cuda_fp16.h>
#include <cstdint>

#define BDIM 1024
#define HDIM 1024
#define DIN  128
#define TLEN 16
#define BH   (BDIM*HDIM)

// ---------------- device scratch ----------------
__device__ float g_ss[BDIM], g_rs[BDIM];
__device__ __half g_x_hi[BDIM*DIN], g_x_lo[BDIM*DIN];
__device__ __half g_cT_hi[HDIM*DIN], g_cT_lo[HDIM*DIN];
__device__ __half g_WsT_hi[BH], g_WsT_lo[BH];   // lo scaled by 1024
__device__ __half g_WlT[BH], g_WrT[BH], g_WqlT[BH];
__device__ __half g_syn_hi[BH], g_syn_lo[BH];
__device__ __half g_liqA[BH], g_qA[BH];
__device__ float g_ic[BH], g_ic2[BH], g_drive[BH], g_qenh[BH];
__device__ unsigned g_sp_min[4], g_sp_max[4];
__device__ unsigned g_cp_min[128], g_cp_max[128];

// ---------------- helpers ----------------
__device__ __forceinline__ unsigned fenc(float v) {
    unsigned u = __float_as_uint(v);
    return u ^ (((int)u >> 31) | 0x80000000u);
}
__device__ __forceinline__ float fdec(unsigned k) {
    unsigned u = (k & 0x80000000u) ? (k ^ 0x80000000u) : ~k;
    return __uint_as_float(u);
}
__device__ __forceinline__ void mma16(float* d, const uint32_t* a, const uint32_t* b) {
    asm volatile("mma.sync.aligned.m16n8k16.row.col.f32.f16.f16.f32 "
                 "{%0,%1,%2,%3}, {%4,%5,%6,%7}, {%8,%9}, {%0,%1,%2,%3};"
                 : "+f"(d[0]), "+f"(d[1]), "+f"(d[2]), "+f"(d[3])
                 : "r"(a[0]), "r"(a[1]), "r"(a[2]), "r"(a[3]), "r"(b[0]), "r"(b[1]));
}
__device__ __forceinline__ int compute_noclip() {
    unsigned sn = 0xFFFFFFFFu, sx = 0u, cn = 0xFFFFFFFFu, cx = 0u;
    #pragma unroll
    for (int i = 0; i < 4; ++i) { sn = min(sn, g_sp_min[i]); sx = max(sx, g_sp_max[i]); }
    for (int i = 0; i < 128; ++i) { cn = min(cn, g_cp_min[i]); cx = max(cx, g_cp_max[i]); }
    float smin = fdec(sn), smax = fdec(sx), cmin = fdec(cn), cmax = fdec(cx);
    return (cmin + smin >= 0.1f && cmax + smax <= 3.0f) ? 1 : 0;
}
__device__ __forceinline__ void h_split(float v, __half& hi, __half& lo, float scale) {
    hi = __float2half_rn(v);
    lo = __float2half_rn((v - __half2float(hi)) * scale);
}
__device__ __forceinline__ float tanh_fast(float x) {
    float xc = fminf(fmaxf(x, -12.f), 12.f);
    float e = __expf(2.f * xc);
    return __fdividef(e - 1.f, e + 1.f);
}

// ======================================================================
// k_prep: all independent prep in one launch, role by blockIdx.x
// ======================================================================
#define PREP_BLOCKS 9348
__global__ __launch_bounds__(256) void k_prep(const float* __restrict__ x,
                                              const float* __restrict__ liq,
                                              const float* __restrict__ q,
                                              const float* __restrict__ noise,
                                              const float* __restrict__ sh,
                                              const float* __restrict__ cond,
                                              const float* __restrict__ Ws,
                                              const float* __restrict__ Wl,
                                              const float* __restrict__ Wr,
                                              const float* __restrict__ Wql,
                                              float* __restrict__ outq) {
    __shared__ float t[32][33];
    __shared__ unsigned redn[256], redx[256];
    const int bid = blockIdx.x, tid = threadIdx.x;

    if (bid < 4) {                                  // ---- ss/rs + spike stats
        int b = bid * 256 + tid;
        float ss = 0.f;
        #pragma unroll
        for (int tt = 0; tt < TLEN; ++tt)
            ss = fmaf(sh[b * TLEN + tt], expf(-0.1f * (float)tt), ss);
        float rs = 0.f;
        for (int d = 0; d < DIN; ++d) rs += x[b * DIN + d];
        g_ss[b] = ss; g_rs[b] = rs;
        unsigned k = fenc(0.01f * ss);
        redn[tid] = k; redx[tid] = k; __syncthreads();
        for (int s = 128; s > 0; s >>= 1) {
            if (tid < s) { redn[tid] = min(redn[tid], redn[tid + s]); redx[tid] = max(redx[tid], redx[tid + s]); }
            __syncthreads();
        }
        if (tid == 0) { g_sp_min[bid] = redn[0]; g_sp_max[bid] = redx[0]; }
    } else if (bid < 132) {                         // ---- cond T+split + stats
        int i = bid - 4;
        int h0 = (i & 31) * 32, d0 = (i >> 5) * 32;
        int tx = tid & 31, ty = tid >> 5;
        float ln = 3.4e38f, lx = -3.4e38f;
        #pragma unroll
        for (int r = 0; r < 4; ++r) {
            float v = cond[(d0 + ty + 8 * r) * HDIM + h0 + tx];
            t[ty + 8 * r][tx] = v; ln = fminf(ln, v); lx = fmaxf(lx, v);
        }
        redn[tid] = fenc(ln); redx[tid] = fenc(lx); __syncthreads();
        for (int s = 128; s > 0; s >>= 1) {
            if (tid < s) { redn[tid] = min(redn[tid], redn[tid + s]); redx[tid] = max(redx[tid], redx[tid + s]); }
            __syncthreads();
        }
        if (tid == 0) { g_cp_min[i] = redn[0]; g_cp_max[i] = redx[0]; }
        #pragma unroll
        for (int r = 0; r < 4; ++r) {
            int o = (h0 + ty + 8 * r) * DIN + d0 + tx;
            h_split(t[tx][ty + 8 * r], g_cT_hi[o], g_cT_lo[o], 1.f);
        }
    } else if (bid < 4228) {                        // ---- weight transpose
        int i = bid - 132;
        int zz = i >> 10, rem = i & 1023;
        const float* W = zz == 0 ? Ws : zz == 1 ? Wl : zz == 2 ? Wr : Wql;
        int n0 = (rem & 31) * 32, k0 = (rem >> 5) * 32;
        int tx = tid & 31, ty = tid >> 5;
        #pragma unroll
        for (int r = 0; r < 4; ++r) t[ty + 8 * r][tx] = W[(k0 + ty + 8 * r) * HDIM + n0 + tx];
        __syncthreads();
        #pragma unroll
        for (int r = 0; r < 4; ++r) {
            float v = t[tx][ty + 8 * r];
            int o = (n0 + ty + 8 * r) * HDIM + k0 + tx;
            if (zz == 0) h_split(v, g_WsT_hi[o], g_WsT_lo[o], 1024.f);
            else if (zz == 1) g_WlT[o] = __float2half_rn(v);
            else if (zz == 2) g_WrT[o] = __float2half_rn(v);
            else g_WqlT[o] = __float2half_rn(v);
        }
    } else if (bid < 8324) {                        // ---- liq round + x split
        int i = (bid - 4228) * 256 + tid;
        g_liqA[i] = __float2half_rn(liq[i]);
        if (i < BDIM * DIN) h_split(x[i], g_x_hi[i], g_x_lo[i], 1.f);
    } else {                                        // ---- qnorm
        __shared__ float red[256];
        int b = bid - 8324;
        const float coh = expf(-0.00066666666666666664f);
        const float dec = 0.0015811388300841898f;
        float e[4]; float ss = 0.f;
        #pragma unroll
        for (int it = 0; it < 4; ++it) {
            int idx = b * HDIM + tid + it * 256;
            float v = q[idx] * coh + noise[idx] * dec;
            e[it] = v; ss += v * v;
        }
        red[tid] = ss; __syncthreads();
        for (int s = 128; s > 0; s >>= 1) { if (tid < s) red[tid] += red[tid + s]; __syncthreads(); }
        float den = sqrtf(red[0]) + 1e-8f;
        #pragma unroll
        for (int it = 0; it < 4; ++it) {
            int idx = b * HDIM + tid + it * 256;
            float v = e[it] / den;
            outq[idx] = v;
            g_qA[idx] = __float2half_rn(v);
        }
    }
}

// ======================================================================
// k_mma: fp16 m16n8k16, double-buffered static smem, CTA 128x128
//   mode 0: z0 ic (2 segs -> g_ic, 1 scaled seg -> g_ic2)
//           z1 drive (2 segs -> g_drive) + qenh (1 seg -> g_qenh)
//   mode 1: syn 3-term (K=128 segs) + rank-1 corr -> split write
// ======================================================================
#define SMH 40   // smem stride in halfs

__global__ __launch_bounds__(256, 1) void k_mma(int mode, const float* __restrict__ x,
                                                const float* __restrict__ cond) {
    __shared__ __align__(16) __half smA[2][128 * SMH];
    __shared__ __align__(16) __half smB[2][128 * SMH];
    __shared__ int s_noclip;
    const int tid = threadIdx.x, wid = tid >> 5, lane = tid & 31;
    const int m0 = blockIdx.y * 128, n0 = blockIdx.x * 128;
    const int wm0 = (wid & 1) * 64, wn0 = (wid >> 1) * 32;
    const int gr = lane >> 2, t4 = lane & 3;
    const int z = blockIdx.z;

    if (mode == 1) {
        if (tid == 0) s_noclip = compute_noclip();
        __syncthreads();
        if (!s_noclip) {   // exact SIMT fallback (clip binds) — correctness path
            int m = m0 + (tid & 127), nh = tid >> 7;
            float s = 0.01f * g_ss[m];
            for (int n = n0 + nh * 64; n < n0 + nh * 64 + 64; ++n) {
                float acc = 0.f;
                for (int d = 0; d < DIN; ++d)
                    acc = fmaf(x[m * DIN + d], fminf(fmaxf(cond[d * HDIM + n] + s, 0.1f), 3.0f), acc);
                size_t o = (size_t)m * HDIM + n;
                h_split(acc, g_syn_hi[o], g_syn_lo[o], 1.f);
            }
            return;
        }
    }

    const __half *Aseg[3], *Bseg[3];
    float* Cf[3] = {nullptr, nullptr, nullptr};
    int ldA, ipern;
    if (mode == 0) {
        ldA = HDIM; ipern = 32;
        if (z == 0) {
            Aseg[0] = g_syn_hi; Bseg[0] = g_WsT_hi;
            Aseg[1] = g_syn_lo; Bseg[1] = g_WsT_hi;
            Aseg[2] = g_syn_hi; Bseg[2] = g_WsT_lo;
            Cf[1] = g_ic; Cf[2] = g_ic2;
        } else {
            Aseg[0] = g_syn_hi; Bseg[0] = g_WlT;
            Aseg[1] = g_liqA;   Bseg[1] = g_WrT;
            Aseg[2] = g_qA;     Bseg[2] = g_WqlT;
            Cf[1] = g_drive; Cf[2] = g_qenh;
        }
    } else {
        ldA = DIN; ipern = 4;
        Aseg[0] = g_x_hi; Bseg[0] = g_cT_hi;
        Aseg[1] = g_x_lo; Bseg[1] = g_cT_hi;
        Aseg[2] = g_x_hi; Bseg[2] = g_cT_lo;
    }
    const int NT = 3 * ipern;

    float acc[4][4][4];
    #pragma unroll
    for (int a = 0; a < 4; ++a)
        #pragma unroll
        for (int b = 0; b < 4; ++b)
            #pragma unroll
            for (int c = 0; c < 4; ++c) acc[a][b][c] = 0.f;

    const int lr = tid >> 2, lc8 = (tid & 3) * 8;    // 64 rows/pass, 8-half cols
    uint4 ra[2], rb[2];
    {   // iter 0 -> buffer 0
        #pragma unroll
        for (int i = 0; i < 2; ++i) {
            int r = lr + i * 64;
            ra[i] = *(const uint4*)(Aseg[0] + (size_t)(m0 + r) * ldA + lc8);
            rb[i] = *(const uint4*)(Bseg[0] + (size_t)(n0 + r) * ldA + lc8);
        }
        #pragma unroll
        for (int i = 0; i < 2; ++i) {
            int r = lr + i * 64;
            *(uint4*)&smA[0][r * SMH + lc8] = ra[i];
            *(uint4*)&smB[0][r * SMH + lc8] = rb[i];
        }
    }
    __syncthreads();

    #pragma unroll 1
    for (int it = 0; it < NT; ++it) {
        const int cur = it & 1;
        const __half* As = smA[cur];
        const __half* Bs = smB[cur];
        if (it + 1 < NT) {
            int seg = (it + 1) / ipern, kk = ((it + 1) % ipern) * 32;
            #pragma unroll
            for (int i = 0; i < 2; ++i) {
                int r = lr + i * 64;
                ra[i] = *(const uint4*)(Aseg[seg] + (size_t)(m0 + r) * ldA + kk + lc8);
                rb[i] = *(const uint4*)(Bseg[seg] + (size_t)(n0 + r) * ldA + kk + lc8);
            }
        }
        #pragma unroll
        for (int kc = 0; kc < 2; ++kc) {
            const int kb = kc * 16 + 2 * t4;
            uint32_t af[4][4], bf[4][2];
            #pragma unroll
            for (int mt = 0; mt < 4; ++mt) {
                int m = wm0 + mt * 16 + gr;
                af[mt][0] = *(const uint32_t*)&As[m * SMH + kb];
                af[mt][1] = *(const uint32_t*)&As[(m + 8) * SMH + kb];
                af[mt][2] = *(const uint32_t*)&As[m * SMH + kb + 8];
                af[mt][3] = *(const uint32_t*)&As[(m + 8) * SMH + kb + 8];
            }
            #pragma unroll
            for (int nt = 0; nt < 4; ++nt) {
                int n = wn0 + nt * 8 + gr;
                bf[nt][0] = *(const uint32_t*)&Bs[n * SMH + kb];
                bf[nt][1] = *(const uint32_t*)&Bs[n * SMH + kb + 8];
            }
            #pragma unroll
            for (int mt = 0; mt < 4; ++mt)
                #pragma unroll
                for (int nt = 0; nt < 4; ++nt)
                    mma16(acc[mt][nt], af[mt], bf[nt]);
        }
        if (mode == 0 && ((it + 1) % ipern == 0)) {
            float* C = Cf[it / ipern];
            if (C) {
                #pragma unroll
                for (int mt = 0; mt < 4; ++mt) {
                    int m = m0 + wm0 + mt * 16 + gr;
                    #pragma unroll
                    for (int nt = 0; nt < 4; ++nt) {
                        int n = n0 + wn0 + nt * 8 + t4 * 2;
                        *(float2*)(C + (size_t)m * HDIM + n) = make_float2(acc[mt][nt][0], acc[mt][nt][1]);
                        *(float2*)(C + (size_t)(m + 8) * HDIM + n) = make_float2(acc[mt][nt][2], acc[mt][nt][3]);
                    }
                }
                #pragma unroll
                for (int a = 0; a < 4; ++a)
                    #pragma unroll
                    for (int b = 0; b < 4; ++b)
                        #pragma unroll
                        for (int c = 0; c < 4; ++c) acc[a][b][c] = 0.f;
            }
        }
        if (it + 1 < NT) {
            #pragma unroll
            for (int i = 0; i < 2; ++i) {
                int r = lr + i * 64;
                *(uint4*)&smA[cur ^ 1][r * SMH + lc8] = ra[i];
                *(uint4*)&smB[cur ^ 1][r * SMH + lc8] = rb[i];
            }
        }
        __syncthreads();
    }

    if (mode == 1) {   // syn epilogue: rank-1 correction + fp16 split write
        #pragma unroll
        for (int mt = 0; mt < 4; ++mt) {
            int m = m0 + wm0 + mt * 16 + gr;
            float c0 = 0.01f * g_ss[m] * g_rs[m];
            float c1 = 0.01f * g_ss[m + 8] * g_rs[m + 8];
            #pragma unroll
            for (int nt = 0; nt < 4; ++nt) {
                int n = n0 + wn0 + nt * 8 + t4 * 2;
                #pragma unroll
                for (int e = 0; e < 4; ++e) {
                    int mm = (e < 2) ? m : m + 8;
                    float v = acc[mt][nt][e] + ((e < 2) ? c0 : c1);
                    size_t o = (size_t)mm * HDIM + n + (e & 1);
                    h_split(v, g_syn_hi[o], g_syn_lo[o], 1.f);
                }
            }
        }
    }
}

// ---------------- final fused epilogue (fast math, shuffle reduce) ----------------
__global__ __launch_bounds__(256) void k_final(const float* __restrict__ mp,
                                               const float* __restrict__ refr_in,
                                               const float* __restrict__ liquid,
                                               const float* __restrict__ taup,
                                               const float* __restrict__ shist,
                                               float* __restrict__ out_fused,
                                               float* __restrict__ out_enh,
                                               float* __restrict__ out_mem,
                                               float* __restrict__ out_refr,
                                               float* __restrict__ out_hist) {
    __shared__ float wsum[8];
    const int b = blockIdx.x, tid = threadIdx.x;
    const float coh = expf(-0.00066666666666666664f);
    float ssum = 0.f;
    #pragma unroll
    for (int it = 0; it < 4; ++it) {
        const int h = tid + it * 256, idx = b * HDIM + h;
        float ic = g_ic[idx] + 9.765625e-4f * g_ic2[idx];
        float drive = g_drive[idx];
        float r = fmaxf(refr_in[idx] - 0.1f, 0.f);
        bool act = (r == 0.f);
        float mem = mp[idx] * 0.95f + (act ? ic * 0.1f : 0.f);
        bool sp = (mem > 0.8f) && act;
        float spike = sp ? 1.f : 0.f;
        out_mem[idx] = sp ? 0.f : mem;
        out_refr[idx] = sp ? 2.f : r;
        float sig = __fdividef(1.f, 1.f + __expf(-taup[h]));
        float tau = 2.f + 23.f * sig;
        float lq = liquid[idx];
        float nl = lq + 0.1f * (tanh_fast(drive) - lq) * __fdividef(1.f, tau);
        float enh = nl + 0.1f * (g_qenh[idx] * coh * 0.85f);
        out_enh[idx] = enh;
        out_fused[idx] = spike * (1.f + 0.1f * tanh_fast(enh));
        ssum += spike;
    }
    #pragma unroll
    for (int o = 16; o; o >>= 1) ssum += __shfl_xor_sync(~0u, ssum, o);
    if ((tid & 31) == 0) wsum[tid >> 5] = ssum;
    __syncthreads();
    if (tid < TLEN - 1) {
        out_hist[b * TLEN + tid] = shist[b * TLEN + tid + 1];
    } else if (tid == TLEN - 1) {
        float t = 0.f;
        #pragma unroll
        for (int i = 0; i < 8; ++i) t += wsum[i];
        out_hist[b * TLEN + TLEN - 1] = t * (1.0f / 1024.0f);
    }
}

// ---------------- launch ----------------
extern "C" void kernel_launch(void* const* d_in, const int* in_sizes, int n_in,
                              void* d_out, int out_size) {
    const float* x      = (const float*)d_in[0];
    const float* liquid = (const float*)d_in[1];
    const float* qstate = (const float*)d_in[2];
    const float* mp     = (const float*)d_in[3];
    const float* refr   = (const float*)d_in[4];
    const float* shist  = (const float*)d_in[5];
    const float* noise  = (const float*)d_in[6];
    const float* cond   = (const float*)d_in[7];
    const float* taup   = (const float*)d_in[8];
    const float* W_l    = (const float*)d_in[9];
    const float* W_r    = (const float*)d_in[10];
    const float* W_s    = (const float*)d_in[11];
    const float* W_ql   = (const float*)d_in[12];

    float* out       = (float*)d_out;
    float* out_fused = out;
    float* out_enh   = out + (size_t)BH;
    float* out_q     = out + (size_t)2 * BH;
    float* out_mem   = out + (size_t)3 * BH;
    float* out_refr  = out + (size_t)4 * BH;
    float* out_hist  = out + (size_t)5 * BH;

    k_prep<<<PREP_BLOCKS, 256>>>(x, liquid, qstate, noise, shist, cond,
                                 W_s, W_l, W_r, W_ql, out_q);
    k_mma<<<dim3(8, 8), 256>>>(1, x, cond);
    k_mma<<<dim3(8, 8, 2), 256>>>(0, x, cond);
    k_final<<<BDIM, 256>>>(mp, refr, liquid, taup, shist,
                           out_fused, out_enh, out_mem, out_refr, out_hist);
}